// round 2
// baseline (speedup 1.0000x reference)
#include <cuda_runtime.h>
#include <cstdint>
#include <cstddef>

// ---------------- problem constants ----------------
#define BATCH   16384
#define SEQ     15
#define DIM     512
#define UNITS   32
#define NQK     64
#define TOTROWS (BATCH * SEQ)          // 245760

// ---------------- kernel A (GEMM) tiling ----------------
#define A_ROWS    128
#define A_THREADS 256
#define A_GRID    (TOTROWS / A_ROWS)   // 1920
#define KCHUNK    32
#define NCHUNKS   (DIM / KCHUNK)       // 16
#define XS_STRIDE 36                   // 144B rows: 16B aligned, conflict-free frags
#define WS_STRIDE 36
#define XS_FLOATS (A_ROWS * XS_STRIDE) // 4608
#define WS_FLOATS (NQK * WS_STRIDE)    // 2304
#define A_SMEM_FLOATS (2 * XS_FLOATS + 2 * WS_FLOATS)   // 13824
#define A_SMEM_BYTES  (A_SMEM_FLOATS * 4)               // 55296

// ---------------- kernel B (attention) ----------------
#define B_WARPS   4
#define B_THREADS 128
#define B_GRID    (BATCH / B_WARPS)    // 4096
#define QK_ST     65                   // padded stride: bank = (i+u)%32
#define EA_ST     16

// ---------------- scratch ----------------
__device__ float g_qk[(size_t)TOTROWS * NQK];   // 62.9 MB
__device__ float g_WT[NQK * DIM];               // [n][k], n<32: Wt, n>=32: Wx

// ---------------- helpers ----------------
__device__ __forceinline__ void cp16(void* dst, const void* src) {
    uint32_t d = (uint32_t)__cvta_generic_to_shared(dst);
    asm volatile("cp.async.cg.shared.global [%0], [%1], 16;" :: "r"(d), "l"(src));
}
#define CP_COMMIT() asm volatile("cp.async.commit_group;")
#define CP_WAIT1()  asm volatile("cp.async.wait_group 1;")
#define CP_WAIT0()  asm volatile("cp.async.wait_group 0;")

__device__ __forceinline__ void mma_tf32(float* c,
                                         uint32_t a0, uint32_t a1, uint32_t a2, uint32_t a3,
                                         uint32_t b0, uint32_t b1) {
    asm volatile(
        "mma.sync.aligned.m16n8k8.row.col.f32.tf32.tf32.f32 "
        "{%0,%1,%2,%3}, {%4,%5,%6,%7}, {%8,%9}, {%0,%1,%2,%3};"
        : "+f"(c[0]), "+f"(c[1]), "+f"(c[2]), "+f"(c[3])
        : "r"(a0), "r"(a1), "r"(a2), "r"(a3), "r"(b0), "r"(b1));
}

__device__ __forceinline__ float rcp_fast(float v) {
    float r;
    asm("rcp.approx.f32 %0, %1;" : "=f"(r) : "f"(v));
    return r;
}

// ================= kernel 0: build W^T =================
__global__ void prep_wt_kernel(const float* __restrict__ Wt,
                               const float* __restrict__ Wx) {
    int idx = blockIdx.x * 256 + threadIdx.x;     // 0..32767
    int n = idx >> 9;                              // 0..63
    int k = idx & 511;
    g_WT[idx] = (n < UNITS) ? Wt[k * UNITS + n] : Wx[k * UNITS + (n - UNITS)];
}

// ================= kernel A: qk = x @ [Wt|Wx] + bh =================
__global__ __launch_bounds__(A_THREADS, 3)
void gemm_qk_kernel(const float* __restrict__ x,
                    const float* __restrict__ bh) {
    extern __shared__ float sm[];
    float* xsb[2] = { sm, sm + XS_FLOATS };
    float* wsb[2] = { sm + 2 * XS_FLOATS, sm + 2 * XS_FLOATS + WS_FLOATS };

    const int tid  = threadIdx.x;
    const int lane = tid & 31;
    const int w    = tid >> 5;
    const long long rowbase = (long long)blockIdx.x * A_ROWS;

    // issue one k-chunk stage into buffer b
    auto issue = [&](int b, int kc) {
        float* xs = xsb[b];
        float* ws = wsb[b];
        #pragma unroll
        for (int r = 0; r < 4; r++) {
            int f   = tid + A_THREADS * r;   // 0..1023 float4 slots
            int row = f >> 3;                // 0..127
            int c4  = f & 7;
            cp16(xs + row * XS_STRIDE + c4 * 4,
                 x + (rowbase + row) * DIM + kc + c4 * 4);
        }
        #pragma unroll
        for (int r = 0; r < 2; r++) {
            int e  = tid + A_THREADS * r;    // 0..511
            int n  = e >> 3;                 // 0..63
            int c4 = e & 7;
            cp16(ws + n * WS_STRIDE + c4 * 4,
                 g_WT + n * DIM + kc + c4 * 4);
        }
        CP_COMMIT();
    };

    issue(0, 0);
    issue(1, KCHUNK);

    float acc[8][4];
    #pragma unroll
    for (int n = 0; n < 8; n++)
        #pragma unroll
        for (int q = 0; q < 4; q++) acc[n][q] = 0.f;

    const int g  = lane >> 2;
    const int tg = lane & 3;

    for (int c = 0; c < NCHUNKS; c++) {
        float* xs = xsb[c & 1];
        float* ws = wsb[c & 1];
        if (c == NCHUNKS - 1) { CP_WAIT0(); } else { CP_WAIT1(); }
        __syncthreads();

        #pragma unroll
        for (int k8 = 0; k8 < 4; k8++) {
            const int kb = k8 * 8;
            const float* ar = xs + (w * 16 + g) * XS_STRIDE + kb + tg;
            uint32_t a0 = __float_as_uint(ar[0]);
            uint32_t a1 = __float_as_uint(ar[8 * XS_STRIDE]);
            uint32_t a2 = __float_as_uint(ar[4]);
            uint32_t a3 = __float_as_uint(ar[8 * XS_STRIDE + 4]);
            #pragma unroll
            for (int nt = 0; nt < 8; nt++) {
                const float* br = ws + (nt * 8 + g) * WS_STRIDE + kb + tg;
                mma_tf32(acc[nt], a0, a1, a2, a3,
                         __float_as_uint(br[0]), __float_as_uint(br[4]));
            }
        }
        __syncthreads();
        if (c + 2 < NCHUNKS) issue(c & 1, (c + 2) * KCHUNK);
    }

    // epilogue: +bh on q columns, store to scratch
    const int r0 = w * 16 + g;
    const int r1 = r0 + 8;
    #pragma unroll
    for (int nt = 0; nt < 8; nt++) {
        int cc = nt * 8 + tg * 2;
        float b0 = (cc     < UNITS) ? __ldg(bh + cc)     : 0.f;
        float b1 = (cc + 1 < UNITS) ? __ldg(bh + cc + 1) : 0.f;
        float2 v0 = make_float2(acc[nt][0] + b0, acc[nt][1] + b1);
        float2 v1 = make_float2(acc[nt][2] + b0, acc[nt][3] + b1);
        *(float2*)(g_qk + (size_t)(rowbase + r0) * NQK + cc) = v0;
        *(float2*)(g_qk + (size_t)(rowbase + r1) * NQK + cc) = v1;
    }
}

// ================= kernel B: e/softmax/AV =================
__global__ __launch_bounds__(B_THREADS, 6)
void attn_kernel(const float* __restrict__ x,
                 const float* __restrict__ Wa,
                 const float* __restrict__ ba,
                 float* __restrict__ out) {
    __shared__ float qs[B_WARPS][SEQ * QK_ST];
    __shared__ float ea[B_WARPS][SEQ * EA_ST];
    __shared__ float was[UNITS];

    const int tid  = threadIdx.x;
    const int lane = tid & 31;
    const int w    = tid >> 5;
    const int batch = blockIdx.x * B_WARPS + w;

    if (tid < UNITS) was[tid] = Wa[tid];
    const float bav = __ldg(ba);
    __syncthreads();   // was visible to all warps

    // ---- stage qk[15][64] for this batch ----
    const float* qg = g_qk + (size_t)batch * SEQ * NQK;
    for (int p = lane; p < SEQ * NQK / 4; p += 32) {   // 240 float4 slots
        float4 v = *(const float4*)(qg + p * 4);
        int row = p >> 4;
        int c4  = p & 15;
        float* d = &qs[w][row * QK_ST + c4 * 4];
        d[0] = v.x; d[1] = v.y; d[2] = v.z; d[3] = v.w;
    }
    __syncwarp();

    // per-thread sum of Wa
    float sWa = 0.f;
    #pragma unroll
    for (int u = 0; u < UNITS; u++) sWa += was[u];

    // ---- e = Wa . tanh(q_i + k_j) + ba + mask ----
    // tanh(z) = 1 - 2/(exp(2z)+1)  -> e = sWa - 2*Σ wa_u/(exp(2z)+1) + ba + mask
    for (int p = lane; p < SEQ * SEQ; p += 32) {
        int i = p / SEQ;
        int j = p - i * SEQ;
        const float* qi = &qs[w][i * QK_ST];
        const float* kj = &qs[w][j * QK_ST + UNITS];
        float s = 0.f;
        #pragma unroll
        for (int u = 0; u < UNITS; u++) {
            float z = qi[u] + kj[u];
            float t = __expf(2.f * z);          // FMUL + MUFU.EX2
            float r = rcp_fast(t + 1.f);        // FADD + MUFU.RCP
            s = fmaf(was[u], r, s);
        }
        float mask = (i == j) ? -10000.f : -fabsf((float)(i - j));
        ea[w][i * EA_ST + j] = sWa - 2.f * s + bav + mask;
    }
    __syncwarp();

    // ---- softmax over j (lane i handles row i) ----
    if (lane < SEQ) {
        const int i = lane;
        float m = -1e30f;
        #pragma unroll
        for (int j = 0; j < SEQ; j++) m = fmaxf(m, ea[w][i * EA_ST + j]);
        float ex[SEQ];
        float sum = 0.f;
        #pragma unroll
        for (int j = 0; j < SEQ; j++) {
            ex[j] = __expf(ea[w][i * EA_ST + j] - m);
            sum += ex[j];
        }
        float inv = 1.f / sum;
        #pragma unroll
        for (int j = 0; j < SEQ; j++) ea[w][i * EA_ST + j] = ex[j] * inv;
    }
    __syncwarp();

    // ---- v = a @ x : persistent av[15], stream x rows ----
    const float* xb = x   + (size_t)batch * SEQ * DIM;
    float*       ob = out + (size_t)batch * SEQ * DIM;

    #pragma unroll 1
    for (int dc = 0; dc < DIM; dc += 128) {
        const int col = dc + lane * 4;
        float4 av[SEQ];
        {
            float4 x0 = *(const float4*)(xb + col);
            #pragma unroll
            for (int i = 0; i < SEQ; i++) {
                float a = ea[w][i * EA_ST + 0];
                av[i].x = a * x0.x; av[i].y = a * x0.y;
                av[i].z = a * x0.z; av[i].w = a * x0.w;
            }
        }
        #pragma unroll
        for (int j = 1; j < SEQ; j++) {
            float4 xj = *(const float4*)(xb + j * DIM + col);
            #pragma unroll
            for (int i = 0; i < SEQ; i++) {
                float a = ea[w][i * EA_ST + j];
                av[i].x = fmaf(a, xj.x, av[i].x);
                av[i].y = fmaf(a, xj.y, av[i].y);
                av[i].z = fmaf(a, xj.z, av[i].z);
                av[i].w = fmaf(a, xj.w, av[i].w);
            }
        }
        #pragma unroll
        for (int i = 0; i < SEQ; i++)
            *(float4*)(ob + i * DIM + col) = av[i];
    }
}

// ================= launch =================
extern "C" void kernel_launch(void* const* d_in, const int* in_sizes, int n_in,
                              void* d_out, int out_size) {
    const float* x  = (const float*)d_in[0];
    const float* Wt = (const float*)d_in[1];
    const float* Wx = (const float*)d_in[2];
    const float* bh = (const float*)d_in[3];
    const float* Wa = (const float*)d_in[4];
    const float* ba = (const float*)d_in[5];
    float* out = (float*)d_out;

    cudaFuncSetAttribute(gemm_qk_kernel,
                         cudaFuncAttributeMaxDynamicSharedMemorySize, A_SMEM_BYTES);

    prep_wt_kernel<<<128, 256>>>(Wt, Wx);
    gemm_qk_kernel<<<A_GRID, A_THREADS, A_SMEM_BYTES>>>(x, bh);
    attn_kernel<<<B_GRID, B_THREADS>>>(x, Wa, ba, out);
}

// round 3
// speedup vs baseline: 1.5523x; 1.5523x over previous
#include <cuda_runtime.h>
#include <cstdint>
#include <cstddef>

// ---------------- problem constants ----------------
#define BATCH   16384
#define SEQ     15
#define DIM     512
#define UNITS   32
#define NQK     64
#define TOTROWS (BATCH * SEQ)          // 245760

// ---------------- kernel A (GEMM) tiling ----------------
#define A_ROWS    128
#define A_THREADS 256
#define A_GRID    (TOTROWS / A_ROWS)   // 1920
#define KCHUNK    32
#define NCHUNKS   (DIM / KCHUNK)       // 16
#define XS_STRIDE 36
#define WS_STRIDE 36
#define XS_FLOATS (A_ROWS * XS_STRIDE) // 4608
#define WS_FLOATS (NQK * WS_STRIDE)    // 2304
#define A_SMEM_FLOATS (2 * XS_FLOATS + 2 * WS_FLOATS)   // 13824
#define A_SMEM_BYTES  (A_SMEM_FLOATS * 4)               // 55296

// ---------------- kernel B (attention) ----------------
#define B_WARPS   4
#define B_THREADS 128
#define B_GRID    (BATCH / B_WARPS)    // 4096
#define QK_ST     65
#define EA_ST     16

// ---------------- scratch ----------------
__device__ float g_qk[(size_t)TOTROWS * NQK];   // 62.9 MB
__device__ float g_WT[NQK * DIM];               // [n][k]

// ---------------- helpers ----------------
__device__ __forceinline__ void cp16(void* dst, const void* src) {
    uint32_t d = (uint32_t)__cvta_generic_to_shared(dst);
    asm volatile("cp.async.cg.shared.global [%0], [%1], 16;" :: "r"(d), "l"(src));
}
#define CP_COMMIT() asm volatile("cp.async.commit_group;")
#define CP_WAIT1()  asm volatile("cp.async.wait_group 1;")
#define CP_WAIT0()  asm volatile("cp.async.wait_group 0;")

__device__ __forceinline__ void mma_tf32(float* c,
                                         uint32_t a0, uint32_t a1, uint32_t a2, uint32_t a3,
                                         uint32_t b0, uint32_t b1) {
    asm volatile(
        "mma.sync.aligned.m16n8k8.row.col.f32.tf32.tf32.f32 "
        "{%0,%1,%2,%3}, {%4,%5,%6,%7}, {%8,%9}, {%0,%1,%2,%3};"
        : "+f"(c[0]), "+f"(c[1]), "+f"(c[2]), "+f"(c[3])
        : "r"(a0), "r"(a1), "r"(a2), "r"(a3), "r"(b0), "r"(b1));
}

__device__ __forceinline__ float rcp_fast(float v) {
    float r;
    asm("rcp.approx.f32 %0, %1;" : "=f"(r) : "f"(v));
    return r;
}

// ================= kernel 0: build W^T =================
__global__ void prep_wt_kernel(const float* __restrict__ Wt,
                               const float* __restrict__ Wx) {
    int idx = blockIdx.x * 256 + threadIdx.x;     // 0..32767
    int n = idx >> 9;
    int k = idx & 511;
    g_WT[idx] = (n < UNITS) ? Wt[k * UNITS + n] : Wx[k * UNITS + (n - UNITS)];
}

// ================= kernel A: qk = x @ [Wt|Wx] + bh =================
__global__ __launch_bounds__(A_THREADS, 3)
void gemm_qk_kernel(const float* __restrict__ x,
                    const float* __restrict__ bh) {
    extern __shared__ float sm[];
    float* xsb[2] = { sm, sm + XS_FLOATS };
    float* wsb[2] = { sm + 2 * XS_FLOATS, sm + 2 * XS_FLOATS + WS_FLOATS };

    const int tid  = threadIdx.x;
    const int lane = tid & 31;
    const int w    = tid >> 5;
    const long long rowbase = (long long)blockIdx.x * A_ROWS;

    auto issue = [&](int b, int kc) {
        float* xs = xsb[b];
        float* ws = wsb[b];
        #pragma unroll
        for (int r = 0; r < 4; r++) {
            int f   = tid + A_THREADS * r;
            int row = f >> 3;
            int c4  = f & 7;
            cp16(xs + row * XS_STRIDE + c4 * 4,
                 x + (rowbase + row) * DIM + kc + c4 * 4);
        }
        #pragma unroll
        for (int r = 0; r < 2; r++) {
            int e  = tid + A_THREADS * r;
            int n  = e >> 3;
            int c4 = e & 7;
            cp16(ws + n * WS_STRIDE + c4 * 4,
                 g_WT + n * DIM + kc + c4 * 4);
        }
        CP_COMMIT();
    };

    issue(0, 0);
    issue(1, KCHUNK);

    float acc[8][4];
    #pragma unroll
    for (int n = 0; n < 8; n++)
        #pragma unroll
        for (int q = 0; q < 4; q++) acc[n][q] = 0.f;

    const int g  = lane >> 2;
    const int tg = lane & 3;

    for (int c = 0; c < NCHUNKS; c++) {
        float* xs = xsb[c & 1];
        float* ws = wsb[c & 1];
        if (c == NCHUNKS - 1) { CP_WAIT0(); } else { CP_WAIT1(); }
        __syncthreads();

        #pragma unroll
        for (int k8 = 0; k8 < 4; k8++) {
            const int kb = k8 * 8;
            const float* ar = xs + (w * 16 + g) * XS_STRIDE + kb + tg;
            uint32_t a0 = __float_as_uint(ar[0]);
            uint32_t a1 = __float_as_uint(ar[8 * XS_STRIDE]);
            uint32_t a2 = __float_as_uint(ar[4]);
            uint32_t a3 = __float_as_uint(ar[8 * XS_STRIDE + 4]);
            #pragma unroll
            for (int nt = 0; nt < 8; nt++) {
                const float* br = ws + (nt * 8 + g) * WS_STRIDE + kb + tg;
                mma_tf32(acc[nt], a0, a1, a2, a3,
                         __float_as_uint(br[0]), __float_as_uint(br[4]));
            }
        }
        __syncthreads();
        if (c + 2 < NCHUNKS) issue(c & 1, (c + 2) * KCHUNK);
    }

    const int r0 = w * 16 + g;
    const int r1 = r0 + 8;
    #pragma unroll
    for (int nt = 0; nt < 8; nt++) {
        int cc = nt * 8 + tg * 2;
        float b0 = (cc     < UNITS) ? __ldg(bh + cc)     : 0.f;
        float b1 = (cc + 1 < UNITS) ? __ldg(bh + cc + 1) : 0.f;
        float2 v0 = make_float2(acc[nt][0] + b0, acc[nt][1] + b1);
        float2 v1 = make_float2(acc[nt][2] + b0, acc[nt][3] + b1);
        *(float2*)(g_qk + (size_t)(rowbase + r0) * NQK + cc) = v0;
        *(float2*)(g_qk + (size_t)(rowbase + r1) * NQK + cc) = v1;
    }
}

// ================= kernel B: e/softmax/AV =================
// launch_bounds(128,4): 128 regs/thread -> av[15] float4 accumulators stay in
// registers (the (128,6)=84-reg cap last round spilled them into the j-loop).
__global__ __launch_bounds__(B_THREADS, 4)
void attn_kernel(const float* __restrict__ x,
                 const float* __restrict__ Wa,
                 const float* __restrict__ ba,
                 float* __restrict__ out) {
    __shared__ float qs[B_WARPS][SEQ * QK_ST];
    __shared__ float ea[B_WARPS][SEQ * EA_ST];
    __shared__ float was[UNITS];

    const int tid  = threadIdx.x;
    const int lane = tid & 31;
    const int w    = tid >> 5;
    const int batch = blockIdx.x * B_WARPS + w;

    if (tid < UNITS) was[tid] = Wa[tid];
    const float bav = __ldg(ba);
    __syncthreads();

    // ---- stage qk[15][64] for this batch ----
    const float* qg = g_qk + (size_t)batch * SEQ * NQK;
    for (int p = lane; p < SEQ * NQK / 4; p += 32) {
        float4 v = *(const float4*)(qg + p * 4);
        int row = p >> 4;
        int c4  = p & 15;
        float* d = &qs[w][row * QK_ST + c4 * 4];
        d[0] = v.x; d[1] = v.y; d[2] = v.z; d[3] = v.w;
    }
    __syncwarp();

    float sWa = 0.f;
    #pragma unroll
    for (int u = 0; u < UNITS; u++) sWa += was[u];

    // ---- e = Wa . tanh(q_i + k_j) + ba + mask ----
    // tanh(z) = 1 - 2/(exp(2z)+1)
    for (int p = lane; p < SEQ * SEQ; p += 32) {
        int i = p / SEQ;
        int j = p - i * SEQ;
        const float* qi = &qs[w][i * QK_ST];
        const float* kj = &qs[w][j * QK_ST + UNITS];
        float s = 0.f;
        #pragma unroll
        for (int u = 0; u < UNITS; u++) {
            float z = qi[u] + kj[u];
            float t = __expf(2.f * z);
            float r = rcp_fast(t + 1.f);
            s = fmaf(was[u], r, s);
        }
        float mask = (i == j) ? -10000.f : -fabsf((float)(i - j));
        ea[w][i * EA_ST + j] = sWa - 2.f * s + bav + mask;
    }
    __syncwarp();

    // ---- softmax over j ----
    if (lane < SEQ) {
        const int i = lane;
        float m = -1e30f;
        #pragma unroll
        for (int j = 0; j < SEQ; j++) m = fmaxf(m, ea[w][i * EA_ST + j]);
        float ex[SEQ];
        float sum = 0.f;
        #pragma unroll
        for (int j = 0; j < SEQ; j++) {
            ex[j] = __expf(ea[w][i * EA_ST + j] - m);
            sum += ex[j];
        }
        float inv = 1.f / sum;
        #pragma unroll
        for (int j = 0; j < SEQ; j++) ea[w][i * EA_ST + j] = ex[j] * inv;
    }
    __syncwarp();

    // ---- v = a @ x : persistent av[15], stream x rows ----
    const float* xb = x   + (size_t)batch * SEQ * DIM;
    float*       ob = out + (size_t)batch * SEQ * DIM;

    #pragma unroll 1
    for (int dc = 0; dc < DIM; dc += 128) {
        const int col = dc + lane * 4;
        float4 av[SEQ];
        {
            float4 x0 = *(const float4*)(xb + col);
            #pragma unroll
            for (int i = 0; i < SEQ; i++) {
                float a = ea[w][i * EA_ST + 0];
                av[i].x = a * x0.x; av[i].y = a * x0.y;
                av[i].z = a * x0.z; av[i].w = a * x0.w;
            }
        }
        #pragma unroll
        for (int j = 1; j < SEQ; j++) {
            float4 xj = *(const float4*)(xb + j * DIM + col);
            #pragma unroll
            for (int i = 0; i < SEQ; i++) {
                float a = ea[w][i * EA_ST + j];
                av[i].x = fmaf(a, xj.x, av[i].x);
                av[i].y = fmaf(a, xj.y, av[i].y);
                av[i].z = fmaf(a, xj.z, av[i].z);
                av[i].w = fmaf(a, xj.w, av[i].w);
            }
        }
        #pragma unroll
        for (int i = 0; i < SEQ; i++)
            *(float4*)(ob + i * DIM + col) = av[i];
    }
}

// ================= launch =================
extern "C" void kernel_launch(void* const* d_in, const int* in_sizes, int n_in,
                              void* d_out, int out_size) {
    const float* x  = (const float*)d_in[0];
    const float* Wt = (const float*)d_in[1];
    const float* Wx = (const float*)d_in[2];
    const float* bh = (const float*)d_in[3];
    const float* Wa = (const float*)d_in[4];
    const float* ba = (const float*)d_in[5];
    float* out = (float*)d_out;

    cudaFuncSetAttribute(gemm_qk_kernel,
                         cudaFuncAttributeMaxDynamicSharedMemorySize, A_SMEM_BYTES);

    prep_wt_kernel<<<128, 256>>>(Wt, Wx);
    gemm_qk_kernel<<<A_GRID, A_THREADS, A_SMEM_BYTES>>>(x, bh);
    attn_kernel<<<B_GRID, B_THREADS>>>(x, Wa, ba, out);
}

// round 4
// speedup vs baseline: 2.3683x; 1.5257x over previous
#include <cuda_runtime.h>
#include <cstdint>
#include <cstddef>

// ---------------- problem constants ----------------
#define BATCH   16384
#define SEQ     15
#define DIM     512
#define UNITS   32
#define NQK     64
#define TOTROWS (BATCH * SEQ)          // 245760

// ---------------- kernel A (GEMM) tiling ----------------
#define A_ROWS    128
#define A_THREADS 256
#define A_GRID    (TOTROWS / A_ROWS)   // 1920
#define KCHUNK    32
#define NCHUNKS   (DIM / KCHUNK)       // 16
#define XS_STRIDE 36                   // x tile: [row][k], padded
#define WS_STRIDE 68                   // W tile: [k][n] (n=0..63), padded
#define XS_FLOATS (A_ROWS * XS_STRIDE) // 4608
#define WS_FLOATS (KCHUNK * WS_STRIDE) // 2176
#define A_SMEM_FLOATS (2 * XS_FLOATS + 2 * WS_FLOATS)   // 13568
#define A_SMEM_BYTES  (A_SMEM_FLOATS * 4)               // 54272

// ---------------- kernel B (attention) ----------------
#define B_WARPS   4
#define B_THREADS 128
#define B_GRID    (BATCH / B_WARPS)    // 4096
#define QK_ST     65
#define EA_ST     16

// ---------------- scratch ----------------
__device__ float g_qk[(size_t)TOTROWS * NQK];   // 62.9 MB

// ---------------- helpers ----------------
__device__ __forceinline__ void cp16(void* dst, const void* src) {
    uint32_t d = (uint32_t)__cvta_generic_to_shared(dst);
    asm volatile("cp.async.cg.shared.global [%0], [%1], 16;" :: "r"(d), "l"(src));
}
#define CP_COMMIT() asm volatile("cp.async.commit_group;")
#define CP_WAIT1()  asm volatile("cp.async.wait_group 1;")
#define CP_WAIT0()  asm volatile("cp.async.wait_group 0;")

__device__ __forceinline__ void mma_tf32(float* c,
                                         uint32_t a0, uint32_t a1, uint32_t a2, uint32_t a3,
                                         uint32_t b0, uint32_t b1) {
    asm volatile(
        "mma.sync.aligned.m16n8k8.row.col.f32.tf32.tf32.f32 "
        "{%0,%1,%2,%3}, {%4,%5,%6,%7}, {%8,%9}, {%0,%1,%2,%3};"
        : "+f"(c[0]), "+f"(c[1]), "+f"(c[2]), "+f"(c[3])
        : "r"(a0), "r"(a1), "r"(a2), "r"(a3), "r"(b0), "r"(b1));
}

__device__ __forceinline__ float rcp_fast(float v) {
    float r;
    asm("rcp.approx.f32 %0, %1;" : "=f"(r) : "f"(v));
    return r;
}

// ================= kernel A: qk = x @ [Wt|Wx] + bh =================
__global__ __launch_bounds__(A_THREADS, 3)
void gemm_qk_kernel(const float* __restrict__ x,
                    const float* __restrict__ Wt,
                    const float* __restrict__ Wx,
                    const float* __restrict__ bh) {
    extern __shared__ float sm[];
    float* xsb[2] = { sm, sm + XS_FLOATS };
    float* wsb[2] = { sm + 2 * XS_FLOATS, sm + 2 * XS_FLOATS + WS_FLOATS };

    const int tid  = threadIdx.x;
    const int lane = tid & 31;
    const int w    = tid >> 5;
    const long long rowbase = (long long)blockIdx.x * A_ROWS;

    // stage one k-chunk: x tile [128 rows][32 k] and W tile [32 k][64 n]
    auto issue = [&](int b, int kc) {
        float* xs = xsb[b];
        float* ws = wsb[b];
        #pragma unroll
        for (int r = 0; r < 4; r++) {
            int f   = tid + A_THREADS * r;   // 0..1023 float4 slots
            int row = f >> 3;                // 0..127
            int c4  = f & 7;                 // 0..7
            cp16(xs + row * XS_STRIDE + c4 * 4,
                 x + (rowbase + row) * DIM + kc + c4 * 4);
        }
        #pragma unroll
        for (int r = 0; r < 2; r++) {
            int e  = tid + A_THREADS * r;    // 0..511
            int k  = e >> 4;                 // 0..31
            int n4 = e & 15;                 // 0..15 (16 float4 groups over n=64)
            const float* src = (n4 < 8)
                ? Wt + (size_t)(kc + k) * UNITS + n4 * 4
                : Wx + (size_t)(kc + k) * UNITS + (n4 - 8) * 4;
            cp16(ws + k * WS_STRIDE + n4 * 4, src);
        }
        CP_COMMIT();
    };

    issue(0, 0);
    issue(1, KCHUNK);

    float acc[8][4];
    #pragma unroll
    for (int n = 0; n < 8; n++)
        #pragma unroll
        for (int q = 0; q < 4; q++) acc[n][q] = 0.f;

    const int g  = lane >> 2;
    const int tg = lane & 3;

    for (int c = 0; c < NCHUNKS; c++) {
        float* xs = xsb[c & 1];
        float* ws = wsb[c & 1];
        if (c == NCHUNKS - 1) { CP_WAIT0(); } else { CP_WAIT1(); }
        __syncthreads();

        #pragma unroll
        for (int k8 = 0; k8 < 4; k8++) {
            const int kb = k8 * 8;
            const float* ar = xs + (w * 16 + g) * XS_STRIDE + kb + tg;
            uint32_t a0 = __float_as_uint(ar[0]);
            uint32_t a1 = __float_as_uint(ar[8 * XS_STRIDE]);
            uint32_t a2 = __float_as_uint(ar[4]);
            uint32_t a3 = __float_as_uint(ar[8 * XS_STRIDE + 4]);
            // B[k][n] layout: thread (g,tg) needs B[kb+tg][n] and B[kb+tg+4][n]
            const float* br = ws + (kb + tg) * WS_STRIDE + g;
            #pragma unroll
            for (int nt = 0; nt < 8; nt++) {
                mma_tf32(acc[nt], a0, a1, a2, a3,
                         __float_as_uint(br[nt * 8]),
                         __float_as_uint(br[4 * WS_STRIDE + nt * 8]));
            }
        }
        __syncthreads();
        if (c + 2 < NCHUNKS) issue(c & 1, (c + 2) * KCHUNK);
    }

    // epilogue: +bh on q columns (n<32), store to scratch
    const int r0 = w * 16 + g;
    const int r1 = r0 + 8;
    #pragma unroll
    for (int nt = 0; nt < 8; nt++) {
        int cc = nt * 8 + tg * 2;
        float b0 = (cc     < UNITS) ? __ldg(bh + cc)     : 0.f;
        float b1 = (cc + 1 < UNITS) ? __ldg(bh + cc + 1) : 0.f;
        float2 v0 = make_float2(acc[nt][0] + b0, acc[nt][1] + b1);
        float2 v1 = make_float2(acc[nt][2] + b0, acc[nt][3] + b1);
        *(float2*)(g_qk + (size_t)(rowbase + r0) * NQK + cc) = v0;
        *(float2*)(g_qk + (size_t)(rowbase + r1) * NQK + cc) = v1;
    }
}

// ================= kernel B: e/softmax/AV =================
// float2 accumulators -> ~45-55 live regs -> (128,8) = 64 regs, 32 warps/SM.
__global__ __launch_bounds__(B_THREADS, 8)
void attn_kernel(const float* __restrict__ x,
                 const float* __restrict__ Wa,
                 const float* __restrict__ ba,
                 float* __restrict__ out) {
    __shared__ float qs[B_WARPS][SEQ * QK_ST];
    __shared__ float ea[B_WARPS][SEQ * EA_ST];
    __shared__ float was[UNITS];

    const int tid  = threadIdx.x;
    const int lane = tid & 31;
    const int w    = tid >> 5;
    const int batch = blockIdx.x * B_WARPS + w;

    if (tid < UNITS) was[tid] = Wa[tid];
    const float bav = __ldg(ba);
    __syncthreads();

    // ---- stage qk[15][64] for this batch ----
    const float* qg = g_qk + (size_t)batch * SEQ * NQK;
    for (int p = lane; p < SEQ * NQK / 4; p += 32) {
        float4 v = *(const float4*)(qg + p * 4);
        int row = p >> 4;
        int c4  = p & 15;
        float* d = &qs[w][row * QK_ST + c4 * 4];
        d[0] = v.x; d[1] = v.y; d[2] = v.z; d[3] = v.w;
    }
    __syncwarp();

    float sWa = 0.f;
    #pragma unroll
    for (int u = 0; u < UNITS; u++) sWa += was[u];

    // ---- e = Wa . tanh(q_i + k_j) + ba + mask ----
    // tanh(z) = 1 - 2/(exp(2z)+1)
    for (int p = lane; p < SEQ * SEQ; p += 32) {
        int i = p / SEQ;
        int j = p - i * SEQ;
        const float* qi = &qs[w][i * QK_ST];
        const float* kj = &qs[w][j * QK_ST + UNITS];
        float s = 0.f;
        #pragma unroll
        for (int u = 0; u < UNITS; u++) {
            float z = qi[u] + kj[u];
            float t = __expf(2.f * z);
            float r = rcp_fast(t + 1.f);
            s = fmaf(was[u], r, s);
        }
        float mask = (i == j) ? -10000.f : -fabsf((float)(i - j));
        ea[w][i * EA_ST + j] = sWa - 2.f * s + bav + mask;
    }
    __syncwarp();

    // ---- softmax over j ----
    if (lane < SEQ) {
        const int i = lane;
        float m = -1e30f;
        #pragma unroll
        for (int j = 0; j < SEQ; j++) m = fmaxf(m, ea[w][i * EA_ST + j]);
        float ex[SEQ];
        float sum = 0.f;
        #pragma unroll
        for (int j = 0; j < SEQ; j++) {
            ex[j] = __expf(ea[w][i * EA_ST + j] - m);
            sum += ex[j];
        }
        float inv = 1.f / sum;
        #pragma unroll
        for (int j = 0; j < SEQ; j++) ea[w][i * EA_ST + j] = ex[j] * inv;
    }
    __syncwarp();

    // ---- v = a @ x : float2 accumulators, streaming loads/stores ----
    const float* xb = x   + (size_t)batch * SEQ * DIM;
    float*       ob = out + (size_t)batch * SEQ * DIM;

    #pragma unroll 1
    for (int dc = 0; dc < DIM; dc += 64) {
        const int col = dc + lane * 2;
        float2 av[SEQ];
        {
            float2 x0 = __ldcs((const float2*)(xb + col));
            #pragma unroll
            for (int i = 0; i < SEQ; i++) {
                float a = ea[w][i * EA_ST + 0];
                av[i].x = a * x0.x;
                av[i].y = a * x0.y;
            }
        }
        #pragma unroll
        for (int j = 1; j < SEQ; j++) {
            float2 xj = __ldcs((const float2*)(xb + j * DIM + col));
            #pragma unroll
            for (int i = 0; i < SEQ; i++) {
                float a = ea[w][i * EA_ST + j];
                av[i].x = fmaf(a, xj.x, av[i].x);
                av[i].y = fmaf(a, xj.y, av[i].y);
            }
        }
        #pragma unroll
        for (int i = 0; i < SEQ; i++)
            __stcs((float2*)(ob + i * DIM + col), av[i]);
    }
}

// ================= launch =================
extern "C" void kernel_launch(void* const* d_in, const int* in_sizes, int n_in,
                              void* d_out, int out_size) {
    const float* x  = (const float*)d_in[0];
    const float* Wt = (const float*)d_in[1];
    const float* Wx = (const float*)d_in[2];
    const float* bh = (const float*)d_in[3];
    const float* Wa = (const float*)d_in[4];
    const float* ba = (const float*)d_in[5];
    float* out = (float*)d_out;

    cudaFuncSetAttribute(gemm_qk_kernel,
                         cudaFuncAttributeMaxDynamicSharedMemorySize, A_SMEM_BYTES);

    gemm_qk_kernel<<<A_GRID, A_THREADS, A_SMEM_BYTES>>>(x, Wt, Wx, bh);
    attn_kernel<<<B_GRID, B_THREADS>>>(x, Wa, ba, out);
}

// round 5
// speedup vs baseline: 3.0743x; 1.2981x over previous
#include <cuda_runtime.h>
#include <cstdint>
#include <cstddef>

// ---------------- problem constants ----------------
#define BATCH   16384
#define SEQ     15
#define DIM     512
#define UNITS   32
#define NQK     64
#define TOTROWS (BATCH * SEQ)          // 245760

// ---------------- kernel A (GEMM) tiling ----------------
#define A_ROWS    128
#define A_THREADS 256
#define A_GRID    (TOTROWS / A_ROWS)   // 1920
#define KCHUNK    32
#define NCHUNKS   (DIM / KCHUNK)       // 16
#define XS_STRIDE 36                   // x tile: [row][k], padded
#define WS_STRIDE 68                   // W tile: [k][n], padded
#define XS_FLOATS (A_ROWS * XS_STRIDE) // 4608
#define WS_FLOATS (KCHUNK * WS_STRIDE) // 2176
#define A_SMEM_FLOATS (2 * XS_FLOATS + 2 * WS_FLOATS)   // 13568
#define A_SMEM_BYTES  (A_SMEM_FLOATS * 4)               // 54272

// ---------------- kernel B (attention) ----------------
#define B_WARPS   4
#define B_THREADS 128
#define B_GRID    (BATCH / B_WARPS)    // 4096
#define QK_ST     65
#define EAT_ST    16                   // eat[j][i], i-contiguous

// ---------------- scratch ----------------
__device__ float g_qk[(size_t)TOTROWS * NQK];   // 62.9 MB

// ---------------- helpers ----------------
__device__ __forceinline__ void cp16(void* dst, const void* src) {
    uint32_t d = (uint32_t)__cvta_generic_to_shared(dst);
    asm volatile("cp.async.cg.shared.global [%0], [%1], 16;" :: "r"(d), "l"(src));
}
#define CP_COMMIT() asm volatile("cp.async.commit_group;")
#define CP_WAIT1()  asm volatile("cp.async.wait_group 1;")
#define CP_WAIT0()  asm volatile("cp.async.wait_group 0;")

__device__ __forceinline__ void mma_tf32(float* c,
                                         uint32_t a0, uint32_t a1, uint32_t a2, uint32_t a3,
                                         uint32_t b0, uint32_t b1) {
    asm volatile(
        "mma.sync.aligned.m16n8k8.row.col.f32.tf32.tf32.f32 "
        "{%0,%1,%2,%3}, {%4,%5,%6,%7}, {%8,%9}, {%0,%1,%2,%3};"
        : "+f"(c[0]), "+f"(c[1]), "+f"(c[2]), "+f"(c[3])
        : "r"(a0), "r"(a1), "r"(a2), "r"(a3), "r"(b0), "r"(b1));
}

__device__ __forceinline__ float rcp_fast(float v) {
    float r;
    asm("rcp.approx.f32 %0, %1;" : "=f"(r) : "f"(v));
    return r;
}

// ================= kernel A: qk = x @ [Wt|Wx] + bh =================
__global__ __launch_bounds__(A_THREADS, 4)
void gemm_qk_kernel(const float* __restrict__ x,
                    const float* __restrict__ Wt,
                    const float* __restrict__ Wx,
                    const float* __restrict__ bh) {
    extern __shared__ float sm[];
    float* xsb[2] = { sm, sm + XS_FLOATS };
    float* wsb[2] = { sm + 2 * XS_FLOATS, sm + 2 * XS_FLOATS + WS_FLOATS };

    const int tid  = threadIdx.x;
    const int lane = tid & 31;
    const int w    = tid >> 5;
    const long long rowbase = (long long)blockIdx.x * A_ROWS;

    auto issue = [&](int b, int kc) {
        float* xs = xsb[b];
        float* ws = wsb[b];
        #pragma unroll
        for (int r = 0; r < 4; r++) {
            int f   = tid + A_THREADS * r;
            int row = f >> 3;
            int c4  = f & 7;
            cp16(xs + row * XS_STRIDE + c4 * 4,
                 x + (rowbase + row) * DIM + kc + c4 * 4);
        }
        #pragma unroll
        for (int r = 0; r < 2; r++) {
            int e  = tid + A_THREADS * r;
            int k  = e >> 4;
            int n4 = e & 15;
            const float* src = (n4 < 8)
                ? Wt + (size_t)(kc + k) * UNITS + n4 * 4
                : Wx + (size_t)(kc + k) * UNITS + (n4 - 8) * 4;
            cp16(ws + k * WS_STRIDE + n4 * 4, src);
        }
        CP_COMMIT();
    };

    issue(0, 0);
    issue(1, KCHUNK);

    float acc[8][4];
    #pragma unroll
    for (int n = 0; n < 8; n++)
        #pragma unroll
        for (int q = 0; q < 4; q++) acc[n][q] = 0.f;

    const int g  = lane >> 2;
    const int tg = lane & 3;

    for (int c = 0; c < NCHUNKS; c++) {
        float* xs = xsb[c & 1];
        float* ws = wsb[c & 1];
        if (c == NCHUNKS - 1) { CP_WAIT0(); } else { CP_WAIT1(); }
        __syncthreads();

        #pragma unroll
        for (int k8 = 0; k8 < 4; k8++) {
            const int kb = k8 * 8;
            const float* ar = xs + (w * 16 + g) * XS_STRIDE + kb + tg;
            uint32_t a0 = __float_as_uint(ar[0]);
            uint32_t a1 = __float_as_uint(ar[8 * XS_STRIDE]);
            uint32_t a2 = __float_as_uint(ar[4]);
            uint32_t a3 = __float_as_uint(ar[8 * XS_STRIDE + 4]);
            const float* br = ws + (kb + tg) * WS_STRIDE + g;
            #pragma unroll
            for (int nt = 0; nt < 8; nt++) {
                mma_tf32(acc[nt], a0, a1, a2, a3,
                         __float_as_uint(br[nt * 8]),
                         __float_as_uint(br[4 * WS_STRIDE + nt * 8]));
            }
        }
        __syncthreads();
        if (c + 2 < NCHUNKS) issue(c & 1, (c + 2) * KCHUNK);
    }

    const int r0 = w * 16 + g;
    const int r1 = r0 + 8;
    #pragma unroll
    for (int nt = 0; nt < 8; nt++) {
        int cc = nt * 8 + tg * 2;
        float b0 = (cc     < UNITS) ? __ldg(bh + cc)     : 0.f;
        float b1 = (cc + 1 < UNITS) ? __ldg(bh + cc + 1) : 0.f;
        float2 v0 = make_float2(acc[nt][0] + b0, acc[nt][1] + b1);
        float2 v1 = make_float2(acc[nt][2] + b0, acc[nt][3] + b1);
        *(float2*)(g_qk + (size_t)(rowbase + r0) * NQK + cc) = v0;
        *(float2*)(g_qk + (size_t)(rowbase + r1) * NQK + cc) = v1;
    }
}

// ================= kernel B: e/softmax/AV =================
__global__ __launch_bounds__(B_THREADS, 8)
void attn_kernel(const float* __restrict__ x,
                 const float* __restrict__ Wa,
                 const float* __restrict__ ba,
                 float* __restrict__ out) {
    __shared__ float qs[B_WARPS][SEQ * QK_ST];
    __shared__ float eat[B_WARPS][SEQ * EAT_ST];  // eat[w][j*16 + i]
    __shared__ float was[UNITS];

    const int tid  = threadIdx.x;
    const int lane = tid & 31;
    const int w    = tid >> 5;
    const int batch = blockIdx.x * B_WARPS + w;

    if (tid < UNITS) was[tid] = Wa[tid];
    const float bav = __ldg(ba);
    __syncthreads();

    // ---- stage qk[15][64] for this batch ----
    const float* qg = g_qk + (size_t)batch * SEQ * NQK;
    for (int p = lane; p < SEQ * NQK / 4; p += 32) {
        float4 v = *(const float4*)(qg + p * 4);
        int row = p >> 4;
        int c4  = p & 15;
        float* d = &qs[w][row * QK_ST + c4 * 4];
        d[0] = v.x; d[1] = v.y; d[2] = v.z; d[3] = v.w;
    }
    __syncwarp();

    float sWa = 0.f;
    #pragma unroll
    for (int u = 0; u < UNITS; u++) sWa += was[u];

    // ---- e = Wa . tanh(q_i + k_j) + ba + mask  (written TRANSPOSED) ----
    // tanh(z) = 1 - 2/(exp(2z)+1)
    for (int p = lane; p < SEQ * SEQ; p += 32) {
        int i = p / SEQ;
        int j = p - i * SEQ;
        const float* qi = &qs[w][i * QK_ST];
        const float* kj = &qs[w][j * QK_ST + UNITS];
        float s = 0.f;
        #pragma unroll
        for (int u = 0; u < UNITS; u++) {
            float z = qi[u] + kj[u];
            float t = __expf(2.f * z);
            float r = rcp_fast(t + 1.f);
            s = fmaf(was[u], r, s);
        }
        float mask = (i == j) ? -10000.f : -fabsf((float)(i - j));
        eat[w][j * EAT_ST + i] = sWa - 2.f * s + bav + mask;
    }
    __syncwarp();

    // ---- softmax over j (lane i owns row i; stride-16 accesses) ----
    if (lane < SEQ) {
        const int i = lane;
        float m = -1e30f;
        #pragma unroll
        for (int j = 0; j < SEQ; j++) m = fmaxf(m, eat[w][j * EAT_ST + i]);
        float ex[SEQ];
        float sum = 0.f;
        #pragma unroll
        for (int j = 0; j < SEQ; j++) {
            ex[j] = __expf(eat[w][j * EAT_ST + i] - m);
            sum += ex[j];
        }
        float inv = 1.f / sum;
        #pragma unroll
        for (int j = 0; j < SEQ; j++) eat[w][j * EAT_ST + i] = ex[j] * inv;
    }
    __syncwarp();

    // ---- v = a @ x : float2 accumulators, a rows loaded as float4 ----
    const float* xb = x   + (size_t)batch * SEQ * DIM;
    float*       ob = out + (size_t)batch * SEQ * DIM;

    #pragma unroll 1
    for (int dc = 0; dc < DIM; dc += 64) {
        const int col = dc + lane * 2;
        float2 av[SEQ];
        #pragma unroll
        for (int i = 0; i < SEQ; i++) av[i] = make_float2(0.f, 0.f);

        #pragma unroll
        for (int j = 0; j < SEQ; j++) {
            float2 xj = __ldcs((const float2*)(xb + j * DIM + col));
            const float4* arow = (const float4*)&eat[w][j * EAT_ST];
            float4 A0 = arow[0];   // a[0..3][j]
            float4 A1 = arow[1];   // a[4..7][j]
            float4 A2 = arow[2];   // a[8..11][j]
            float4 A3 = arow[3];   // a[12..15][j] (.w = pad, unused)
            av[0].x  = fmaf(A0.x, xj.x, av[0].x);  av[0].y  = fmaf(A0.x, xj.y, av[0].y);
            av[1].x  = fmaf(A0.y, xj.x, av[1].x);  av[1].y  = fmaf(A0.y, xj.y, av[1].y);
            av[2].x  = fmaf(A0.z, xj.x, av[2].x);  av[2].y  = fmaf(A0.z, xj.y, av[2].y);
            av[3].x  = fmaf(A0.w, xj.x, av[3].x);  av[3].y  = fmaf(A0.w, xj.y, av[3].y);
            av[4].x  = fmaf(A1.x, xj.x, av[4].x);  av[4].y  = fmaf(A1.x, xj.y, av[4].y);
            av[5].x  = fmaf(A1.y, xj.x, av[5].x);  av[5].y  = fmaf(A1.y, xj.y, av[5].y);
            av[6].x  = fmaf(A1.z, xj.x, av[6].x);  av[6].y  = fmaf(A1.z, xj.y, av[6].y);
            av[7].x  = fmaf(A1.w, xj.x, av[7].x);  av[7].y  = fmaf(A1.w, xj.y, av[7].y);
            av[8].x  = fmaf(A2.x, xj.x, av[8].x);  av[8].y  = fmaf(A2.x, xj.y, av[8].y);
            av[9].x  = fmaf(A2.y, xj.x, av[9].x);  av[9].y  = fmaf(A2.y, xj.y, av[9].y);
            av[10].x = fmaf(A2.z, xj.x, av[10].x); av[10].y = fmaf(A2.z, xj.y, av[10].y);
            av[11].x = fmaf(A2.w, xj.x, av[11].x); av[11].y = fmaf(A2.w, xj.y, av[11].y);
            av[12].x = fmaf(A3.x, xj.x, av[12].x); av[12].y = fmaf(A3.x, xj.y, av[12].y);
            av[13].x = fmaf(A3.y, xj.x, av[13].x); av[13].y = fmaf(A3.y, xj.y, av[13].y);
            av[14].x = fmaf(A3.z, xj.x, av[14].x); av[14].y = fmaf(A3.z, xj.y, av[14].y);
        }
        #pragma unroll
        for (int i = 0; i < SEQ; i++)
            __stcs((float2*)(ob + i * DIM + col), av[i]);
    }
}

// ================= launch =================
extern "C" void kernel_launch(void* const* d_in, const int* in_sizes, int n_in,
                              void* d_out, int out_size) {
    const float* x  = (const float*)d_in[0];
    const float* Wt = (const float*)d_in[1];
    const float* Wx = (const float*)d_in[2];
    const float* bh = (const float*)d_in[3];
    const float* Wa = (const float*)d_in[4];
    const float* ba = (const float*)d_in[5];
    float* out = (float*)d_out;

    cudaFuncSetAttribute(gemm_qk_kernel,
                         cudaFuncAttributeMaxDynamicSharedMemorySize, A_SMEM_BYTES);

    gemm_qk_kernel<<<A_GRID, A_THREADS, A_SMEM_BYTES>>>(x, Wt, Wx, bh);
    attn_kernel<<<B_GRID, B_THREADS>>>(x, Wa, ba, out);
}

// round 6
// speedup vs baseline: 3.1009x; 1.0086x over previous
#include <cuda_runtime.h>
#include <cstdint>
#include <cstddef>

// ---------------- problem constants ----------------
#define BATCH   16384
#define SEQ     15
#define DIM     512
#define UNITS   32
#define NQK     64
#define TOTROWS (BATCH * SEQ)          // 245760

// ---------------- kernel A (GEMM) tiling ----------------
#define A_ROWS    128
#define A_THREADS 256
#define A_GRID    (TOTROWS / A_ROWS)   // 1920
#define KCHUNK    32
#define NCHUNKS   (DIM / KCHUNK)       // 16
#define NSTAGE    3
#define XS_STRIDE 36                   // x tile: [row][k], padded
#define WS_STRIDE 68                   // W tile: [k][n], padded
#define XS_FLOATS (A_ROWS * XS_STRIDE) // 4608
#define WS_FLOATS (KCHUNK * WS_STRIDE) // 2176
#define STAGE_FLOATS (XS_FLOATS + WS_FLOATS)            // 6784
#define A_SMEM_FLOATS (NSTAGE * STAGE_FLOATS)           // 20352
#define A_SMEM_BYTES  (A_SMEM_FLOATS * 4)               // 81408

// ---------------- kernel B (attention) ----------------
#define B_WARPS   4
#define B_THREADS 128
#define B_GRID    (BATCH / B_WARPS)    // 4096
#define QK_ST     68                   // 16B-aligned rows for float4 LDS
#define EAT_ST    16                   // eat[j][i], i-contiguous

// ---------------- scratch ----------------
__device__ float g_qk[(size_t)TOTROWS * NQK];   // 62.9 MB

// ---------------- helpers ----------------
__device__ __forceinline__ void cp16(void* dst, const void* src) {
    uint32_t d = (uint32_t)__cvta_generic_to_shared(dst);
    asm volatile("cp.async.cg.shared.global [%0], [%1], 16;" :: "r"(d), "l"(src));
}
#define CP_COMMIT() asm volatile("cp.async.commit_group;")
#define CP_WAIT1()  asm volatile("cp.async.wait_group 1;")
#define CP_WAIT0()  asm volatile("cp.async.wait_group 0;")

__device__ __forceinline__ void mma_tf32(float* c,
                                         uint32_t a0, uint32_t a1, uint32_t a2, uint32_t a3,
                                         uint32_t b0, uint32_t b1) {
    asm volatile(
        "mma.sync.aligned.m16n8k8.row.col.f32.tf32.tf32.f32 "
        "{%0,%1,%2,%3}, {%4,%5,%6,%7}, {%8,%9}, {%0,%1,%2,%3};"
        : "+f"(c[0]), "+f"(c[1]), "+f"(c[2]), "+f"(c[3])
        : "r"(a0), "r"(a1), "r"(a2), "r"(a3), "r"(b0), "r"(b1));
}

__device__ __forceinline__ float rcp_fast(float v) {
    float r;
    asm("rcp.approx.f32 %0, %1;" : "=f"(r) : "f"(v));
    return r;
}

// ================= kernel A: qk = x @ [Wt|Wx] + bh =================
// 3-stage cp.async pipeline, single __syncthreads per chunk.
__global__ __launch_bounds__(A_THREADS, 2)
void gemm_qk_kernel(const float* __restrict__ x,
                    const float* __restrict__ Wt,
                    const float* __restrict__ Wx,
                    const float* __restrict__ bh) {
    extern __shared__ float sm[];

    const int tid  = threadIdx.x;
    const int lane = tid & 31;
    const int w    = tid >> 5;
    const long long rowbase = (long long)blockIdx.x * A_ROWS;

    auto issue = [&](int stage, int kc) {
        float* xs = sm + stage * STAGE_FLOATS;
        float* ws = xs + XS_FLOATS;
        #pragma unroll
        for (int r = 0; r < 4; r++) {
            int f   = tid + A_THREADS * r;
            int row = f >> 3;
            int c4  = f & 7;
            cp16(xs + row * XS_STRIDE + c4 * 4,
                 x + (rowbase + row) * DIM + kc + c4 * 4);
        }
        #pragma unroll
        for (int r = 0; r < 2; r++) {
            int e  = tid + A_THREADS * r;
            int k  = e >> 4;
            int n4 = e & 15;
            const float* src = (n4 < 8)
                ? Wt + (size_t)(kc + k) * UNITS + n4 * 4
                : Wx + (size_t)(kc + k) * UNITS + (n4 - 8) * 4;
            cp16(ws + k * WS_STRIDE + n4 * 4, src);
        }
        CP_COMMIT();
    };

    issue(0, 0);
    issue(1, KCHUNK);

    float acc[8][4];
    #pragma unroll
    for (int n = 0; n < 8; n++)
        #pragma unroll
        for (int q = 0; q < 4; q++) acc[n][q] = 0.f;

    const int g  = lane >> 2;
    const int tg = lane & 3;

    int stage = 0;
    for (int c = 0; c < NCHUNKS; c++) {
        if (c == NCHUNKS - 1) { CP_WAIT0(); } else { CP_WAIT1(); }
        __syncthreads();   // chunk c visible AND all warps done reading buf (c-1)%3

        // prefetch chunk c+2 into buffer (c+2)%3 == (c-1)%3 (safe after sync)
        if (c + 2 < NCHUNKS) {
            int ns = stage + 2; if (ns >= NSTAGE) ns -= NSTAGE;
            issue(ns, (c + 2) * KCHUNK);
        }

        float* xs = sm + stage * STAGE_FLOATS;
        float* ws = xs + XS_FLOATS;

        #pragma unroll
        for (int k8 = 0; k8 < 4; k8++) {
            const int kb = k8 * 8;
            const float* ar = xs + (w * 16 + g) * XS_STRIDE + kb + tg;
            uint32_t a0 = __float_as_uint(ar[0]);
            uint32_t a1 = __float_as_uint(ar[8 * XS_STRIDE]);
            uint32_t a2 = __float_as_uint(ar[4]);
            uint32_t a3 = __float_as_uint(ar[8 * XS_STRIDE + 4]);
            const float* br = ws + (kb + tg) * WS_STRIDE + g;
            #pragma unroll
            for (int nt = 0; nt < 8; nt++) {
                mma_tf32(acc[nt], a0, a1, a2, a3,
                         __float_as_uint(br[nt * 8]),
                         __float_as_uint(br[4 * WS_STRIDE + nt * 8]));
            }
        }
        if (++stage >= NSTAGE) stage -= NSTAGE;
    }

    const int r0 = w * 16 + g;
    const int r1 = r0 + 8;
    #pragma unroll
    for (int nt = 0; nt < 8; nt++) {
        int cc = nt * 8 + tg * 2;
        float b0 = (cc     < UNITS) ? __ldg(bh + cc)     : 0.f;
        float b1 = (cc + 1 < UNITS) ? __ldg(bh + cc + 1) : 0.f;
        float2 v0 = make_float2(acc[nt][0] + b0, acc[nt][1] + b1);
        float2 v1 = make_float2(acc[nt][2] + b0, acc[nt][3] + b1);
        *(float2*)(g_qk + (size_t)(rowbase + r0) * NQK + cc) = v0;
        *(float2*)(g_qk + (size_t)(rowbase + r1) * NQK + cc) = v1;
    }
}

// ================= kernel B: e/softmax/AV =================
__global__ __launch_bounds__(B_THREADS, 8)
void attn_kernel(const float* __restrict__ x,
                 const float* __restrict__ Wa,
                 const float* __restrict__ ba,
                 float* __restrict__ out) {
    __shared__ float qs[B_WARPS][SEQ * QK_ST];
    __shared__ float eat[B_WARPS][SEQ * EAT_ST];  // eat[w][j*16 + i]
    __shared__ float was[UNITS];

    const int tid  = threadIdx.x;
    const int lane = tid & 31;
    const int w    = tid >> 5;
    const int batch = blockIdx.x * B_WARPS + w;

    if (tid < UNITS) was[tid] = Wa[tid];
    const float bav = __ldg(ba);
    __syncthreads();

    // ---- stage qk[15][64] for this batch (rows 16B-aligned at stride 68) ----
    const float* qg = g_qk + (size_t)batch * SEQ * NQK;
    for (int p = lane; p < SEQ * NQK / 4; p += 32) {
        float4 v = __ldcs((const float4*)(qg + p * 4));
        int row = p >> 4;
        int c4  = p & 15;
        *(float4*)&qs[w][row * QK_ST + c4 * 4] = v;
    }
    __syncwarp();

    float sWa = 0.f;
    #pragma unroll
    for (int u = 0; u < UNITS; u++) sWa += was[u];

    // ---- e = Wa . tanh(q_i + k_j) + ba + mask  (written TRANSPOSED) ----
    // tanh(z) = 1 - 2/(exp(2z)+1); vectorized float4 LDS
    for (int p = lane; p < SEQ * SEQ; p += 32) {
        int i = p / SEQ;
        int j = p - i * SEQ;
        const float4* qi = (const float4*)&qs[w][i * QK_ST];
        const float4* kj = (const float4*)&qs[w][j * QK_ST + UNITS];
        const float4* wa4 = (const float4*)was;
        float s = 0.f;
        #pragma unroll
        for (int u4 = 0; u4 < UNITS / 4; u4++) {
            float4 q = qi[u4];
            float4 k = kj[u4];
            float4 wa = wa4[u4];
            float z0 = q.x + k.x, z1 = q.y + k.y, z2 = q.z + k.z, z3 = q.w + k.w;
            s = fmaf(wa.x, rcp_fast(__expf(2.f * z0) + 1.f), s);
            s = fmaf(wa.y, rcp_fast(__expf(2.f * z1) + 1.f), s);
            s = fmaf(wa.z, rcp_fast(__expf(2.f * z2) + 1.f), s);
            s = fmaf(wa.w, rcp_fast(__expf(2.f * z3) + 1.f), s);
        }
        float mask = (i == j) ? -10000.f : -fabsf((float)(i - j));
        eat[w][j * EAT_ST + i] = sWa - 2.f * s + bav + mask;
    }
    __syncwarp();

    // ---- softmax over j (lane i owns row i) ----
    if (lane < SEQ) {
        const int i = lane;
        float m = -1e30f;
        #pragma unroll
        for (int j = 0; j < SEQ; j++) m = fmaxf(m, eat[w][j * EAT_ST + i]);
        float ex[SEQ];
        float sum = 0.f;
        #pragma unroll
        for (int j = 0; j < SEQ; j++) {
            ex[j] = __expf(eat[w][j * EAT_ST + i] - m);
            sum += ex[j];
        }
        float inv = 1.f / sum;
        #pragma unroll
        for (int j = 0; j < SEQ; j++) eat[w][j * EAT_ST + i] = ex[j] * inv;
    }
    __syncwarp();

    // ---- v = a @ x : float2 accumulators, a rows loaded as float4 ----
    const float* xb = x   + (size_t)batch * SEQ * DIM;
    float*       ob = out + (size_t)batch * SEQ * DIM;

    #pragma unroll 1
    for (int dc = 0; dc < DIM; dc += 64) {
        const int col = dc + lane * 2;
        float2 av[SEQ];
        #pragma unroll
        for (int i = 0; i < SEQ; i++) av[i] = make_float2(0.f, 0.f);

        #pragma unroll
        for (int j = 0; j < SEQ; j++) {
            float2 xj = __ldcs((const float2*)(xb + j * DIM + col));
            const float4* arow = (const float4*)&eat[w][j * EAT_ST];
            float4 A0 = arow[0];
            float4 A1 = arow[1];
            float4 A2 = arow[2];
            float4 A3 = arow[3];
            av[0].x  = fmaf(A0.x, xj.x, av[0].x);  av[0].y  = fmaf(A0.x, xj.y, av[0].y);
            av[1].x  = fmaf(A0.y, xj.x, av[1].x);  av[1].y  = fmaf(A0.y, xj.y, av[1].y);
            av[2].x  = fmaf(A0.z, xj.x, av[2].x);  av[2].y  = fmaf(A0.z, xj.y, av[2].y);
            av[3].x  = fmaf(A0.w, xj.x, av[3].x);  av[3].y  = fmaf(A0.w, xj.y, av[3].y);
            av[4].x  = fmaf(A1.x, xj.x, av[4].x);  av[4].y  = fmaf(A1.x, xj.y, av[4].y);
            av[5].x  = fmaf(A1.y, xj.x, av[5].x);  av[5].y  = fmaf(A1.y, xj.y, av[5].y);
            av[6].x  = fmaf(A1.z, xj.x, av[6].x);  av[6].y  = fmaf(A1.z, xj.y, av[6].y);
            av[7].x  = fmaf(A1.w, xj.x, av[7].x);  av[7].y  = fmaf(A1.w, xj.y, av[7].y);
            av[8].x  = fmaf(A2.x, xj.x, av[8].x);  av[8].y  = fmaf(A2.x, xj.y, av[8].y);
            av[9].x  = fmaf(A2.y, xj.x, av[9].x);  av[9].y  = fmaf(A2.y, xj.y, av[9].y);
            av[10].x = fmaf(A2.z, xj.x, av[10].x); av[10].y = fmaf(A2.z, xj.y, av[10].y);
            av[11].x = fmaf(A2.w, xj.x, av[11].x); av[11].y = fmaf(A2.w, xj.y, av[11].y);
            av[12].x = fmaf(A3.x, xj.x, av[12].x); av[12].y = fmaf(A3.x, xj.y, av[12].y);
            av[13].x = fmaf(A3.y, xj.x, av[13].x); av[13].y = fmaf(A3.y, xj.y, av[13].y);
            av[14].x = fmaf(A3.z, xj.x, av[14].x); av[14].y = fmaf(A3.z, xj.y, av[14].y);
        }
        #pragma unroll
        for (int i = 0; i < SEQ; i++)
            __stcs((float2*)(ob + i * DIM + col), av[i]);
    }
}

// ================= launch =================
extern "C" void kernel_launch(void* const* d_in, const int* in_sizes, int n_in,
                              void* d_out, int out_size) {
    const float* x  = (const float*)d_in[0];
    const float* Wt = (const float*)d_in[1];
    const float* Wx = (const float*)d_in[2];
    const float* bh = (const float*)d_in[3];
    const float* Wa = (const float*)d_in[4];
    const float* ba = (const float*)d_in[5];
    float* out = (float*)d_out;

    cudaFuncSetAttribute(gemm_qk_kernel,
                         cudaFuncAttributeMaxDynamicSharedMemorySize, A_SMEM_BYTES);

    gemm_qk_kernel<<<A_GRID, A_THREADS, A_SMEM_BYTES>>>(x, Wt, Wx, bh);
    attn_kernel<<<B_GRID, B_THREADS>>>(x, Wa, ba, out);
}